// round 1
// baseline (speedup 1.0000x reference)
#include <cuda_runtime.h>
#include <math.h>

#define H 256
#define NB_CLASSES 7
#define B_MAX 14000
#define EPS 1e-8f

// Scratch (allocation-free rule: __device__ globals)
__device__ float g_rawret[B_MAX * H];
__device__ float g_rn[B_MAX];
__device__ float g_csum[NB_CLASSES * H];
__device__ float g_ccnt[NB_CLASSES];
__device__ float g_ave[NB_CLASSES * H];
__device__ float g_an[NB_CLASSES];

__device__ __forceinline__ float wred_sum(float v) {
    #pragma unroll
    for (int o = 16; o; o >>= 1) v += __shfl_xor_sync(0xFFFFFFFFu, v, o);
    return v;
}

// ---------------------------------------------------------------------------
// Kernel 0: zero class accumulators
// ---------------------------------------------------------------------------
__global__ void kz() {
    int i = blockIdx.x * blockDim.x + threadIdx.x;
    if (i < NB_CLASSES * H) g_csum[i] = 0.f;
    if (i < NB_CLASSES) g_ccnt[i] = 0.f;
}

// ---------------------------------------------------------------------------
// Kernel 1: per-row. 1 CTA per row b, 256 threads (8 warps).
//   - cooperative load of center (weighted by w_self) into SMEM
//   - warp w gathers neighbors k = w, w+8, ... : applies w_nb / w_nb2,
//     stores to SMEM, computes dot-with-center and sumsq via warp reduce
//   - warp 0 does the K=48 softmax over cosine sims
//   - all threads: weighted sum over k from SMEM, + center -> rawret
//   - block reduce: row norm; RED atomics into class sums
// ---------------------------------------------------------------------------
__global__ void k1(const float* __restrict__ embeds,
                   const float* __restrict__ wself,
                   const float* __restrict__ wnb,
                   const float* __restrict__ wnb2,
                   const int* __restrict__ idx,
                   const int* __restrict__ labels,
                   const int* __restrict__ nbr,
                   const int* __restrict__ nbr2,
                   int K1, int K2) {
    extern __shared__ float sh[];
    const int KT = K1 + K2;
    float* nb_s = sh;                 // KT * H
    float* cen  = sh + KT * H;        // H
    float* dots = cen + H;            // KT
    float* nrms = dots + KT;          // KT
    float* wgt  = nrms + KT;          // KT
    float* red  = wgt + KT;           // 32

    const int b    = blockIdx.x;
    const int tid  = threadIdx.x;
    const int lane = tid & 31;
    const int warp = tid >> 5;

    // center (weighted)
    const int crow = idx[b];
    const float c = embeds[(size_t)crow * H + tid] * wself[tid];
    cen[tid] = c;
    float cs = wred_sum(c * c);
    if (lane == 0) red[warp] = cs;
    __syncthreads();

    // center norm, computed redundantly by all threads (broadcast LDS)
    float cn = 0.f;
    #pragma unroll
    for (int i = 0; i < 8; i++) cn += red[i];
    cn = fmaxf(sqrtf(cn), EPS);

    const float4* cen4 = (const float4*)cen;
    const float4 c0 = cen4[lane];
    const float4 c1 = cen4[lane + 32];

    // gather neighbors: warp w handles k = w, w+8, ...
    for (int k = warp; k < KT; k += 8) {
        const int r = (k < K1) ? nbr[b * K1 + k] : nbr2[b * K2 + (k - K1)];
        const float4* src = (const float4*)(embeds + (size_t)r * H);
        const float4* wv  = (const float4*)((k < K1) ? wnb : wnb2);
        float4 e0 = src[lane];
        float4 e1 = src[lane + 32];
        const float4 w0 = wv[lane];
        const float4 w1 = wv[lane + 32];
        e0.x *= w0.x; e0.y *= w0.y; e0.z *= w0.z; e0.w *= w0.w;
        e1.x *= w1.x; e1.y *= w1.y; e1.z *= w1.z; e1.w *= w1.w;

        float d = e0.x * c0.x + e0.y * c0.y + e0.z * c0.z + e0.w * c0.w
                + e1.x * c1.x + e1.y * c1.y + e1.z * c1.z + e1.w * c1.w;
        float s = e0.x * e0.x + e0.y * e0.y + e0.z * e0.z + e0.w * e0.w
                + e1.x * e1.x + e1.y * e1.y + e1.z * e1.z + e1.w * e1.w;

        float4* dst = (float4*)(nb_s + k * H);
        dst[lane]      = e0;
        dst[lane + 32] = e1;

        d = wred_sum(d);
        s = wred_sum(s);
        if (lane == 0) { dots[k] = d; nrms[k] = s; }
    }
    __syncthreads();

    // softmax over KT cosine sims (warp 0; lane handles k=lane and k=lane+32)
    if (warp == 0) {
        const int ka = lane, kb = lane + 32;
        float cosA = -1e30f, cosB = -1e30f;
        if (ka < KT) cosA = dots[ka] / (cn * fmaxf(sqrtf(nrms[ka]), EPS));
        if (kb < KT) cosB = dots[kb] / (cn * fmaxf(sqrtf(nrms[kb]), EPS));
        float m = fmaxf(cosA, cosB);
        #pragma unroll
        for (int o = 16; o; o >>= 1) m = fmaxf(m, __shfl_xor_sync(0xFFFFFFFFu, m, o));
        float eA = (ka < KT) ? __expf(cosA - m) : 0.f;
        float eB = (kb < KT) ? __expf(cosB - m) : 0.f;
        const float ssum = wred_sum(eA + eB);
        const float inv = 1.f / ssum;
        if (ka < KT) wgt[ka] = eA * inv;
        if (kb < KT) wgt[kb] = eB * inv;
    }
    __syncthreads();

    // weighted sum over k (SMEM, conflict-free) + center
    float acc = 0.f;
    for (int k = 0; k < KT; k++)
        acc = fmaf(wgt[k], nb_s[k * H + tid], acc);
    const float rr = acc + c;

    g_rawret[(size_t)b * H + tid] = rr;

    // row norm
    float rs = wred_sum(rr * rr);
    if (lane == 0) red[warp] = rs;
    __syncthreads();
    if (tid == 0) {
        float t = 0.f;
        #pragma unroll
        for (int i = 0; i < 8; i++) t += red[i];
        g_rn[b] = fmaxf(sqrtf(t), EPS);
    }

    // class accumulation (RED, no return)
    const int lbl = labels[b];
    atomicAdd(&g_csum[lbl * H + tid], rr);
    if (tid == 0) atomicAdd(&g_ccnt[lbl], 1.f);
}

// ---------------------------------------------------------------------------
// Kernel 2: class means + norms. 7 blocks x 256 threads.
// ---------------------------------------------------------------------------
__global__ void k2() {
    __shared__ float red[8];
    const int cc   = blockIdx.x;
    const int tid  = threadIdx.x;
    const int lane = tid & 31;
    const int warp = tid >> 5;
    const float v = g_csum[cc * H + tid] / fmaxf(g_ccnt[cc], 1.f);
    g_ave[cc * H + tid] = v;
    float s = wred_sum(v * v);
    if (lane == 0) red[warp] = s;
    __syncthreads();
    if (tid == 0) {
        float t = 0.f;
        #pragma unroll
        for (int i = 0; i < 8; i++) t += red[i];
        g_an[cc] = fmaxf(sqrtf(t), EPS);
    }
}

// ---------------------------------------------------------------------------
// Kernel 3: output. 1 warp per row, 8 rows per CTA. Class means in SMEM.
// ---------------------------------------------------------------------------
__global__ void k3(float* __restrict__ out, int B) {
    __shared__ float ave_s[NB_CLASSES * H];
    __shared__ float an_s[NB_CLASSES];
    const int tid  = threadIdx.x;
    const int lane = tid & 31;
    const int warp = tid >> 5;
    for (int i = tid; i < NB_CLASSES * H; i += 256) ave_s[i] = g_ave[i];
    if (tid < NB_CLASSES) an_s[tid] = g_an[tid];
    __syncthreads();

    const int b = blockIdx.x * 8 + warp;
    if (b >= B) return;

    const float4* r4 = (const float4*)(g_rawret + (size_t)b * H);
    const float4 ra = r4[lane];
    const float4 rb = r4[lane + 32];

    float d[NB_CLASSES];
    #pragma unroll
    for (int cc = 0; cc < NB_CLASSES; cc++) {
        const float4* a4 = (const float4*)(ave_s + cc * H);
        const float4 a0 = a4[lane];
        const float4 a1 = a4[lane + 32];
        float t = ra.x * a0.x + ra.y * a0.y + ra.z * a0.z + ra.w * a0.w
                + rb.x * a1.x + rb.y * a1.y + rb.z * a1.z + rb.w * a1.w;
        #pragma unroll
        for (int o = 16; o; o >>= 1) t += __shfl_xor_sync(0xFFFFFFFFu, t, o);
        d[cc] = t;
    }

    const float rbn = g_rn[b];
    float m = -1e30f;
    #pragma unroll
    for (int cc = 0; cc < NB_CLASSES; cc++) {
        d[cc] = d[cc] / (rbn * an_s[cc]);
        m = fmaxf(m, d[cc]);
    }
    float s = 0.f;
    #pragma unroll
    for (int cc = 0; cc < NB_CLASSES; cc++) {
        d[cc] = __expf(d[cc] - m);
        s += d[cc];
    }
    const float inv = 1.f / s;
    if (lane < NB_CLASSES) {
        float v = 0.f;
        #pragma unroll
        for (int cc = 0; cc < NB_CLASSES; cc++)
            if (lane == cc) v = d[cc] * inv;
        out[b * NB_CLASSES + lane] = v;
    }
}

// ---------------------------------------------------------------------------
extern "C" void kernel_launch(void* const* d_in, const int* in_sizes, int n_in,
                              void* d_out, int out_size) {
    const float* embeds = (const float*)d_in[0];
    const float* wself  = (const float*)d_in[1];
    const float* wnb    = (const float*)d_in[2];
    const float* wnb2   = (const float*)d_in[3];
    const int*   idx    = (const int*)d_in[4];
    const int*   labels = (const int*)d_in[5];
    const int*   nbr    = (const int*)d_in[6];
    const int*   nbr2   = (const int*)d_in[7];
    float* out = (float*)d_out;

    const int B  = in_sizes[4];
    const int K1 = in_sizes[6] / B;
    const int K2 = in_sizes[7] / B;
    const int KT = K1 + K2;

    const size_t smem = (size_t)(KT * H + H + 3 * KT + 32) * sizeof(float);
    cudaFuncSetAttribute(k1, cudaFuncAttributeMaxDynamicSharedMemorySize, (int)smem);

    kz<<<NB_CLASSES, 256>>>();
    k1<<<B, 256, smem>>>(embeds, wself, wnb, wnb2, idx, labels, nbr, nbr2, K1, K2);
    k2<<<NB_CLASSES, 256>>>();
    k3<<<(B + 7) / 8, 256>>>(out, B);
}

// round 2
// speedup vs baseline: 1.0305x; 1.0305x over previous
#include <cuda_runtime.h>
#include <math.h>

#define H 256
#define NB_CLASSES 7
#define B_MAX 14000
#define EPS 1e-8f

// Scratch (allocation-free rule: __device__ globals)
__device__ float g_rawret[B_MAX * H];
__device__ float g_rn[B_MAX];
__device__ float g_csum[NB_CLASSES * H];
__device__ float g_ccnt[NB_CLASSES];
__device__ float g_ave[NB_CLASSES * H];
__device__ float g_an[NB_CLASSES];

__device__ __forceinline__ float wred_sum(float v) {
    #pragma unroll
    for (int o = 16; o; o >>= 1) v += __shfl_xor_sync(0xFFFFFFFFu, v, o);
    return v;
}

// ---------------------------------------------------------------------------
// Kernel 0: zero class accumulators
// ---------------------------------------------------------------------------
__global__ void kz() {
    int i = blockIdx.x * blockDim.x + threadIdx.x;
    if (i < NB_CLASSES * H) g_csum[i] = 0.f;
    if (i < NB_CLASSES) g_ccnt[i] = 0.f;
}

// ---------------------------------------------------------------------------
// Kernel 1 (specialized K1=16, K2=32): 1 CTA per row, 256 threads (8 warps).
// Warp w handles k = w + 8*j, j=0..5.  All 12 LDG.128 issued up front
// (MLP=12), all 12 warp reductions interleaved (one 5-level butterfly pass).
// ---------------------------------------------------------------------------
template<int K1, int K2>
__global__ void __launch_bounds__(256, 2)
k1s(const float* __restrict__ embeds,
    const float* __restrict__ wself,
    const float* __restrict__ wnb,
    const float* __restrict__ wnb2,
    const int* __restrict__ idx,
    const int* __restrict__ labels,
    const int* __restrict__ nbr,
    const int* __restrict__ nbr2) {
    constexpr int KT = K1 + K2;      // 48
    constexpr int JP = KT / 8;       // 6 k's per warp
    constexpr int J1 = K1 / 8;       // first J1 j's use w_nb

    extern __shared__ float sh[];
    float* nb_s = sh;                 // KT * H
    float* cen  = sh + KT * H;        // H
    float* dots = cen + H;            // KT
    float* nrms = dots + KT;          // KT
    float* wgt  = nrms + KT;          // KT
    float* red  = wgt + KT;           // 32

    const int b    = blockIdx.x;
    const int tid  = threadIdx.x;
    const int lane = tid & 31;
    const int warp = tid >> 5;

    // center (weighted)
    const int crow = idx[b];
    const float c = embeds[(size_t)crow * H + tid] * wself[tid];
    cen[tid] = c;
    float cs = wred_sum(c * c);
    if (lane == 0) red[warp] = cs;
    __syncthreads();

    float cn = 0.f;
    #pragma unroll
    for (int i = 0; i < 8; i++) cn += red[i];
    cn = fmaxf(sqrtf(cn), EPS);

    const float4* cen4 = (const float4*)cen;
    const float4 c0 = cen4[lane];
    const float4 c1 = cen4[lane + 32];

    // --- gather: all indices, then all row loads (batched, MLP=12) ---
    int rows[JP];
    #pragma unroll
    for (int j = 0; j < JP; j++) {
        const int k = warp + 8 * j;
        rows[j] = (j < J1) ? nbr[b * K1 + k] : nbr2[b * K2 + (k - K1)];
    }

    float4 e0[JP], e1[JP];
    #pragma unroll
    for (int j = 0; j < JP; j++) {
        const float4* src = (const float4*)(embeds + (size_t)rows[j] * H);
        e0[j] = src[lane];
        e1[j] = src[lane + 32];
    }

    // neighbor prompt weights (per half)
    const float4* wa4 = (const float4*)wnb;
    const float4* wb4 = (const float4*)wnb2;
    const float4 wa0 = wa4[lane], wa1 = wa4[lane + 32];
    const float4 wb0 = wb4[lane], wb1 = wb4[lane + 32];

    float d[JP], s[JP];
    #pragma unroll
    for (int j = 0; j < JP; j++) {
        const float4 w0 = (j < J1) ? wa0 : wb0;
        const float4 w1 = (j < J1) ? wa1 : wb1;
        e0[j].x *= w0.x; e0[j].y *= w0.y; e0[j].z *= w0.z; e0[j].w *= w0.w;
        e1[j].x *= w1.x; e1[j].y *= w1.y; e1[j].z *= w1.z; e1[j].w *= w1.w;

        d[j] = e0[j].x * c0.x + e0[j].y * c0.y + e0[j].z * c0.z + e0[j].w * c0.w
             + e1[j].x * c1.x + e1[j].y * c1.y + e1[j].z * c1.z + e1[j].w * c1.w;
        s[j] = e0[j].x * e0[j].x + e0[j].y * e0[j].y + e0[j].z * e0[j].z + e0[j].w * e0[j].w
             + e1[j].x * e1[j].x + e1[j].y * e1[j].y + e1[j].z * e1[j].z + e1[j].w * e1[j].w;

        float4* dst = (float4*)(nb_s + (warp + 8 * j) * H);
        dst[lane]      = e0[j];
        dst[lane + 32] = e1[j];
    }

    // interleaved butterfly reductions: 12 independent values, 5 levels
    #pragma unroll
    for (int o = 16; o; o >>= 1) {
        #pragma unroll
        for (int j = 0; j < JP; j++) {
            d[j] += __shfl_xor_sync(0xFFFFFFFFu, d[j], o);
            s[j] += __shfl_xor_sync(0xFFFFFFFFu, s[j], o);
        }
    }
    if (lane == 0) {
        #pragma unroll
        for (int j = 0; j < JP; j++) {
            dots[warp + 8 * j] = d[j];
            nrms[warp + 8 * j] = s[j];
        }
    }
    __syncthreads();

    // softmax over KT cosine sims (warp 0)
    if (warp == 0) {
        const int ka = lane, kb = lane + 32;
        float cosA = -1e30f, cosB = -1e30f;
        if (ka < KT) cosA = dots[ka] / (cn * fmaxf(sqrtf(nrms[ka]), EPS));
        if (kb < KT) cosB = dots[kb] / (cn * fmaxf(sqrtf(nrms[kb]), EPS));
        float m = fmaxf(cosA, cosB);
        #pragma unroll
        for (int o = 16; o; o >>= 1) m = fmaxf(m, __shfl_xor_sync(0xFFFFFFFFu, m, o));
        float eA = (ka < KT) ? __expf(cosA - m) : 0.f;
        float eB = (kb < KT) ? __expf(cosB - m) : 0.f;
        const float ssum = wred_sum(eA + eB);
        const float inv = 1.f / ssum;
        if (ka < KT) wgt[ka] = eA * inv;
        if (kb < KT) wgt[kb] = eB * inv;
    }
    __syncthreads();

    // weighted sum over k (SMEM, conflict-free) + center; 2 accumulators for ILP
    float acc0 = 0.f, acc1 = 0.f;
    #pragma unroll 8
    for (int k = 0; k < KT; k += 2) {
        acc0 = fmaf(wgt[k],     nb_s[k * H + tid],       acc0);
        acc1 = fmaf(wgt[k + 1], nb_s[(k + 1) * H + tid], acc1);
    }
    const float rr = acc0 + acc1 + c;

    g_rawret[(size_t)b * H + tid] = rr;

    float rs = wred_sum(rr * rr);
    if (lane == 0) red[warp] = rs;
    __syncthreads();
    if (tid == 0) {
        float t = 0.f;
        #pragma unroll
        for (int i = 0; i < 8; i++) t += red[i];
        g_rn[b] = fmaxf(sqrtf(t), EPS);
    }

    const int lbl = labels[b];
    atomicAdd(&g_csum[lbl * H + tid], rr);
    if (tid == 0) atomicAdd(&g_ccnt[lbl], 1.f);
}

// ---------------------------------------------------------------------------
// Kernel 1 generic fallback (any K1/K2)
// ---------------------------------------------------------------------------
__global__ void k1g(const float* __restrict__ embeds,
                    const float* __restrict__ wself,
                    const float* __restrict__ wnb,
                    const float* __restrict__ wnb2,
                    const int* __restrict__ idx,
                    const int* __restrict__ labels,
                    const int* __restrict__ nbr,
                    const int* __restrict__ nbr2,
                    int K1, int K2) {
    extern __shared__ float sh[];
    const int KT = K1 + K2;
    float* nb_s = sh;
    float* cen  = sh + KT * H;
    float* dots = cen + H;
    float* nrms = dots + KT;
    float* wgt  = nrms + KT;
    float* red  = wgt + KT;

    const int b    = blockIdx.x;
    const int tid  = threadIdx.x;
    const int lane = tid & 31;
    const int warp = tid >> 5;

    const int crow = idx[b];
    const float c = embeds[(size_t)crow * H + tid] * wself[tid];
    cen[tid] = c;
    float cs = wred_sum(c * c);
    if (lane == 0) red[warp] = cs;
    __syncthreads();

    float cn = 0.f;
    #pragma unroll
    for (int i = 0; i < 8; i++) cn += red[i];
    cn = fmaxf(sqrtf(cn), EPS);

    const float4* cen4 = (const float4*)cen;
    const float4 c0 = cen4[lane];
    const float4 c1 = cen4[lane + 32];

    for (int k = warp; k < KT; k += 8) {
        const int r = (k < K1) ? nbr[b * K1 + k] : nbr2[b * K2 + (k - K1)];
        const float4* src = (const float4*)(embeds + (size_t)r * H);
        const float4* wv  = (const float4*)((k < K1) ? wnb : wnb2);
        float4 e0 = src[lane];
        float4 e1 = src[lane + 32];
        const float4 w0 = wv[lane];
        const float4 w1 = wv[lane + 32];
        e0.x *= w0.x; e0.y *= w0.y; e0.z *= w0.z; e0.w *= w0.w;
        e1.x *= w1.x; e1.y *= w1.y; e1.z *= w1.z; e1.w *= w1.w;

        float d = e0.x * c0.x + e0.y * c0.y + e0.z * c0.z + e0.w * c0.w
                + e1.x * c1.x + e1.y * c1.y + e1.z * c1.z + e1.w * c1.w;
        float s = e0.x * e0.x + e0.y * e0.y + e0.z * e0.z + e0.w * e0.w
                + e1.x * e1.x + e1.y * e1.y + e1.z * e1.z + e1.w * e1.w;

        float4* dst = (float4*)(nb_s + k * H);
        dst[lane]      = e0;
        dst[lane + 32] = e1;

        d = wred_sum(d);
        s = wred_sum(s);
        if (lane == 0) { dots[k] = d; nrms[k] = s; }
    }
    __syncthreads();

    if (warp == 0) {
        const int ka = lane, kb = lane + 32;
        float cosA = -1e30f, cosB = -1e30f;
        if (ka < KT) cosA = dots[ka] / (cn * fmaxf(sqrtf(nrms[ka]), EPS));
        if (kb < KT) cosB = dots[kb] / (cn * fmaxf(sqrtf(nrms[kb]), EPS));
        float m = fmaxf(cosA, cosB);
        #pragma unroll
        for (int o = 16; o; o >>= 1) m = fmaxf(m, __shfl_xor_sync(0xFFFFFFFFu, m, o));
        float eA = (ka < KT) ? __expf(cosA - m) : 0.f;
        float eB = (kb < KT) ? __expf(cosB - m) : 0.f;
        const float ssum = wred_sum(eA + eB);
        const float inv = 1.f / ssum;
        if (ka < KT) wgt[ka] = eA * inv;
        if (kb < KT) wgt[kb] = eB * inv;
    }
    __syncthreads();

    float acc = 0.f;
    for (int k = 0; k < KT; k++)
        acc = fmaf(wgt[k], nb_s[k * H + tid], acc);
    const float rr = acc + c;

    g_rawret[(size_t)b * H + tid] = rr;

    float rs = wred_sum(rr * rr);
    if (lane == 0) red[warp] = rs;
    __syncthreads();
    if (tid == 0) {
        float t = 0.f;
        #pragma unroll
        for (int i = 0; i < 8; i++) t += red[i];
        g_rn[b] = fmaxf(sqrtf(t), EPS);
    }

    const int lbl = labels[b];
    atomicAdd(&g_csum[lbl * H + tid], rr);
    if (tid == 0) atomicAdd(&g_ccnt[lbl], 1.f);
}

// ---------------------------------------------------------------------------
// Kernel 2: class means + norms. 7 blocks x 256 threads.
// ---------------------------------------------------------------------------
__global__ void k2() {
    __shared__ float red[8];
    const int cc   = blockIdx.x;
    const int tid  = threadIdx.x;
    const int lane = tid & 31;
    const int warp = tid >> 5;
    const float v = g_csum[cc * H + tid] / fmaxf(g_ccnt[cc], 1.f);
    g_ave[cc * H + tid] = v;
    float s = wred_sum(v * v);
    if (lane == 0) red[warp] = s;
    __syncthreads();
    if (tid == 0) {
        float t = 0.f;
        #pragma unroll
        for (int i = 0; i < 8; i++) t += red[i];
        g_an[cc] = fmaxf(sqrtf(t), EPS);
    }
}

// ---------------------------------------------------------------------------
// Kernel 3: output. 1 warp per row, 8 rows per CTA.
// All 7 class-dot butterflies interleaved (one 5-level pass).
// ---------------------------------------------------------------------------
__global__ void k3(float* __restrict__ out, int B) {
    __shared__ float ave_s[NB_CLASSES * H];
    __shared__ float an_s[NB_CLASSES];
    const int tid  = threadIdx.x;
    const int lane = tid & 31;
    const int warp = tid >> 5;
    for (int i = tid; i < NB_CLASSES * H; i += 256) ave_s[i] = g_ave[i];
    if (tid < NB_CLASSES) an_s[tid] = g_an[tid];
    __syncthreads();

    const int b = blockIdx.x * 8 + warp;
    if (b >= B) return;

    const float4* r4 = (const float4*)(g_rawret + (size_t)b * H);
    const float4 ra = r4[lane];
    const float4 rb = r4[lane + 32];

    float d[NB_CLASSES];
    #pragma unroll
    for (int cc = 0; cc < NB_CLASSES; cc++) {
        const float4* a4 = (const float4*)(ave_s + cc * H);
        const float4 a0 = a4[lane];
        const float4 a1 = a4[lane + 32];
        d[cc] = ra.x * a0.x + ra.y * a0.y + ra.z * a0.z + ra.w * a0.w
              + rb.x * a1.x + rb.y * a1.y + rb.z * a1.z + rb.w * a1.w;
    }
    // interleaved butterflies: 7 independent reductions, 5 levels
    #pragma unroll
    for (int o = 16; o; o >>= 1) {
        #pragma unroll
        for (int cc = 0; cc < NB_CLASSES; cc++)
            d[cc] += __shfl_xor_sync(0xFFFFFFFFu, d[cc], o);
    }

    const float rbn = g_rn[b];
    float m = -1e30f;
    #pragma unroll
    for (int cc = 0; cc < NB_CLASSES; cc++) {
        d[cc] = d[cc] / (rbn * an_s[cc]);
        m = fmaxf(m, d[cc]);
    }
    float s = 0.f;
    #pragma unroll
    for (int cc = 0; cc < NB_CLASSES; cc++) {
        d[cc] = __expf(d[cc] - m);
        s += d[cc];
    }
    const float inv = 1.f / s;
    if (lane < NB_CLASSES) {
        float v = 0.f;
        #pragma unroll
        for (int cc = 0; cc < NB_CLASSES; cc++)
            if (lane == cc) v = d[cc] * inv;
        out[b * NB_CLASSES + lane] = v;
    }
}

// ---------------------------------------------------------------------------
extern "C" void kernel_launch(void* const* d_in, const int* in_sizes, int n_in,
                              void* d_out, int out_size) {
    const float* embeds = (const float*)d_in[0];
    const float* wself  = (const float*)d_in[1];
    const float* wnb    = (const float*)d_in[2];
    const float* wnb2   = (const float*)d_in[3];
    const int*   idx    = (const int*)d_in[4];
    const int*   labels = (const int*)d_in[5];
    const int*   nbr    = (const int*)d_in[6];
    const int*   nbr2   = (const int*)d_in[7];
    float* out = (float*)d_out;

    const int B  = in_sizes[4];
    const int K1 = in_sizes[6] / B;
    const int K2 = in_sizes[7] / B;
    const int KT = K1 + K2;

    const size_t smem = (size_t)(KT * H + H + 3 * KT + 32) * sizeof(float);

    kz<<<NB_CLASSES, 256>>>();
    if (K1 == 16 && K2 == 32) {
        static int attr_set = 0;
        if (!attr_set) {
            cudaFuncSetAttribute(k1s<16, 32>,
                                 cudaFuncAttributeMaxDynamicSharedMemorySize, (int)smem);
            attr_set = 1;
        }
        k1s<16, 32><<<B, 256, smem>>>(embeds, wself, wnb, wnb2, idx, labels, nbr, nbr2);
    } else {
        cudaFuncSetAttribute(k1g, cudaFuncAttributeMaxDynamicSharedMemorySize, (int)smem);
        k1g<<<B, 256, smem>>>(embeds, wself, wnb, wnb2, idx, labels, nbr, nbr2, K1, K2);
    }
    k2<<<NB_CLASSES, 256>>>();
    k3<<<(B + 7) / 8, 256>>>(out, B);
}

// round 3
// speedup vs baseline: 1.2404x; 1.2037x over previous
#include <cuda_runtime.h>
#include <cuda_fp16.h>
#include <math.h>

#define H 256
#define NB_CLASSES 7
#define B_MAX 14000
#define N_MAX 100000
#define EPS 1e-8f

// Scratch (allocation-free rule: __device__ globals)
__device__ __half g_eh[(size_t)N_MAX * H];      // fp16 copy of embeds (51.2 MB)
__device__ float g_rawret[B_MAX * H];
__device__ float g_rn[B_MAX];
__device__ float g_csum[NB_CLASSES * H];
__device__ float g_ccnt[NB_CLASSES];
__device__ float g_ave[NB_CLASSES * H];
__device__ float g_an[NB_CLASSES];

__device__ __forceinline__ float wred_sum(float v) {
    #pragma unroll
    for (int o = 16; o; o >>= 1) v += __shfl_xor_sync(0xFFFFFFFFu, v, o);
    return v;
}

// ---------------------------------------------------------------------------
// Kernel C: convert embeds fp32 -> fp16 table; block 0 zeroes accumulators.
// One thread handles 8 elements (2x LDG.128 in, 1x STG.128 out).
// ---------------------------------------------------------------------------
__global__ void kc(const float* __restrict__ embeds, int total8) {
    if (blockIdx.x == 0) {
        for (int j = threadIdx.x; j < NB_CLASSES * H; j += blockDim.x) g_csum[j] = 0.f;
        if (threadIdx.x < NB_CLASSES) g_ccnt[threadIdx.x] = 0.f;
    }
    const float4* in4 = (const float4*)embeds;
    uint4* out4 = (uint4*)g_eh;
    for (int i = blockIdx.x * blockDim.x + threadIdx.x; i < total8;
         i += gridDim.x * blockDim.x) {
        float4 a = in4[2 * i];
        float4 b = in4[2 * i + 1];
        union { uint4 u; __half2 h[4]; } pk;
        pk.h[0] = __float22half2_rn(make_float2(a.x, a.y));
        pk.h[1] = __float22half2_rn(make_float2(a.z, a.w));
        pk.h[2] = __float22half2_rn(make_float2(b.x, b.y));
        pk.h[3] = __float22half2_rn(make_float2(b.z, b.w));
        out4[i] = pk.u;
    }
}

// ---------------------------------------------------------------------------
// Kernel 1 (specialized K1=16, K2=32): 1 CTA per row, 256 threads (8 warps).
// Gathers from the fp16 table: ONE LDG.128 per neighbor row per warp.
// Warp w handles k = w + 8*j, j=0..5 (j<2 -> w_nb, else w_nb2).
// Lane covers channels [8*lane, 8*lane+8).
// ---------------------------------------------------------------------------
template<int K1, int K2>
__global__ void __launch_bounds__(256, 3)
k1s(const float* __restrict__ embeds,
    const float* __restrict__ wself,
    const float* __restrict__ wnb,
    const float* __restrict__ wnb2,
    const int* __restrict__ idx,
    const int* __restrict__ labels,
    const int* __restrict__ nbr,
    const int* __restrict__ nbr2) {
    constexpr int KT = K1 + K2;      // 48
    constexpr int JP = KT / 8;       // 6 rows per warp
    constexpr int J1 = K1 / 8;       // first J1 j's use w_nb

    extern __shared__ float sh[];
    __half* nb_h = (__half*)sh;                        // KT*H halves (24 KB)
    float* cen   = (float*)(nb_h + KT * H);            // H
    float* wa_s  = cen + H;                            // H (w_nb)
    float* wb_s  = wa_s + H;                           // H (w_nb2)
    float* dots  = wb_s + H;                           // KT
    float* nrms  = dots + KT;                          // KT
    float* wgt   = nrms + KT;                          // KT
    float* red   = wgt + KT;                           // 8

    const int b    = blockIdx.x;
    const int tid  = threadIdx.x;
    const int lane = tid & 31;
    const int warp = tid >> 5;

    // center (weighted, fp32) + stage prompt weights to SMEM
    const int crow = idx[b];
    const float c = embeds[(size_t)crow * H + tid] * wself[tid];
    cen[tid]  = c;
    wa_s[tid] = wnb[tid];
    wb_s[tid] = wnb2[tid];
    float cs = wred_sum(c * c);
    if (lane == 0) red[warp] = cs;
    __syncthreads();

    float cn = 0.f;
    #pragma unroll
    for (int i = 0; i < 8; i++) cn += red[i];
    cn = fmaxf(sqrtf(cn), EPS);

    // per-lane center channels [8*lane, 8*lane+8)
    const float4 cc0 = ((const float4*)cen)[2 * lane];
    const float4 cc1 = ((const float4*)cen)[2 * lane + 1];

    // gather indices then all row loads (batched, MLP=6 x LDG.128)
    int rows[JP];
    #pragma unroll
    for (int j = 0; j < JP; j++) {
        const int k = warp + 8 * j;
        rows[j] = (j < J1) ? nbr[b * K1 + k] : nbr2[b * K2 + (k - K1)];
    }
    uint4 raw[JP];
    #pragma unroll
    for (int j = 0; j < JP; j++)
        raw[j] = ((const uint4*)(g_eh + (size_t)rows[j] * H))[lane];

    float d[JP], s[JP];
    #pragma unroll
    for (int j = 0; j < JP; j++) {
        const float* wsrc = (j < J1) ? wa_s : wb_s;
        const float4 w0 = ((const float4*)wsrc)[2 * lane];
        const float4 w1 = ((const float4*)wsrc)[2 * lane + 1];

        union { uint4 u; __half2 h[4]; } pk;
        pk.u = raw[j];
        float2 v0 = __half22float2(pk.h[0]);
        float2 v1 = __half22float2(pk.h[1]);
        float2 v2 = __half22float2(pk.h[2]);
        float2 v3 = __half22float2(pk.h[3]);
        v0.x *= w0.x; v0.y *= w0.y; v1.x *= w0.z; v1.y *= w0.w;
        v2.x *= w1.x; v2.y *= w1.y; v3.x *= w1.z; v3.y *= w1.w;

        d[j] = v0.x * cc0.x + v0.y * cc0.y + v1.x * cc0.z + v1.y * cc0.w
             + v2.x * cc1.x + v2.y * cc1.y + v3.x * cc1.z + v3.y * cc1.w;
        s[j] = v0.x * v0.x + v0.y * v0.y + v1.x * v1.x + v1.y * v1.y
             + v2.x * v2.x + v2.y * v2.y + v3.x * v3.x + v3.y * v3.y;

        // store scaled neighbor (fp16) to SMEM
        union { uint4 u; __half2 h[4]; } st;
        st.h[0] = __float22half2_rn(v0);
        st.h[1] = __float22half2_rn(v1);
        st.h[2] = __float22half2_rn(v2);
        st.h[3] = __float22half2_rn(v3);
        ((uint4*)(nb_h + (warp + 8 * j) * H))[lane] = st.u;
    }

    // interleaved butterflies: 12 independent reductions, 5 levels
    #pragma unroll
    for (int o = 16; o; o >>= 1) {
        #pragma unroll
        for (int j = 0; j < JP; j++) {
            d[j] += __shfl_xor_sync(0xFFFFFFFFu, d[j], o);
            s[j] += __shfl_xor_sync(0xFFFFFFFFu, s[j], o);
        }
    }
    if (lane == 0) {
        #pragma unroll
        for (int j = 0; j < JP; j++) {
            dots[warp + 8 * j] = d[j];
            nrms[warp + 8 * j] = s[j];
        }
    }
    __syncthreads();

    // softmax over KT cosine sims (warp 0)
    if (warp == 0) {
        const int ka = lane, kb = lane + 32;
        float cosA = -1e30f, cosB = -1e30f;
        if (ka < KT) cosA = dots[ka] / (cn * fmaxf(sqrtf(nrms[ka]), EPS));
        if (kb < KT) cosB = dots[kb] / (cn * fmaxf(sqrtf(nrms[kb]), EPS));
        float m = fmaxf(cosA, cosB);
        #pragma unroll
        for (int o = 16; o; o >>= 1) m = fmaxf(m, __shfl_xor_sync(0xFFFFFFFFu, m, o));
        float eA = (ka < KT) ? __expf(cosA - m) : 0.f;
        float eB = (kb < KT) ? __expf(cosB - m) : 0.f;
        const float ssum = wred_sum(eA + eB);
        const float inv = 1.f / ssum;
        if (ka < KT) wgt[ka] = eA * inv;
        if (kb < KT) wgt[kb] = eB * inv;
    }
    __syncthreads();

    // weighted sum over k (SMEM fp16) + center
    float acc0 = 0.f, acc1 = 0.f;
    #pragma unroll 8
    for (int k = 0; k < KT; k += 2) {
        acc0 = fmaf(wgt[k],     __half2float(nb_h[k * H + tid]),       acc0);
        acc1 = fmaf(wgt[k + 1], __half2float(nb_h[(k + 1) * H + tid]), acc1);
    }
    const float rr = acc0 + acc1 + c;

    __stcs(&g_rawret[(size_t)b * H + tid], rr);

    float rs = wred_sum(rr * rr);
    if (lane == 0) red[warp] = rs;
    __syncthreads();
    if (tid == 0) {
        float t = 0.f;
        #pragma unroll
        for (int i = 0; i < 8; i++) t += red[i];
        g_rn[b] = fmaxf(sqrtf(t), EPS);
    }

    const int lbl = labels[b];
    atomicAdd(&g_csum[lbl * H + tid], rr);
    if (tid == 0) atomicAdd(&g_ccnt[lbl], 1.f);
}

// ---------------------------------------------------------------------------
// Kernel 1 generic fallback (any K1/K2), fp32 path
// ---------------------------------------------------------------------------
__global__ void k1g(const float* __restrict__ embeds,
                    const float* __restrict__ wself,
                    const float* __restrict__ wnb,
                    const float* __restrict__ wnb2,
                    const int* __restrict__ idx,
                    const int* __restrict__ labels,
                    const int* __restrict__ nbr,
                    const int* __restrict__ nbr2,
                    int K1, int K2) {
    extern __shared__ float sh[];
    const int KT = K1 + K2;
    float* nb_s = sh;
    float* cen  = sh + KT * H;
    float* dots = cen + H;
    float* nrms = dots + KT;
    float* wgt  = nrms + KT;
    float* red  = wgt + KT;

    const int b    = blockIdx.x;
    const int tid  = threadIdx.x;
    const int lane = tid & 31;
    const int warp = tid >> 5;

    const int crow = idx[b];
    const float c = embeds[(size_t)crow * H + tid] * wself[tid];
    cen[tid] = c;
    float cs = wred_sum(c * c);
    if (lane == 0) red[warp] = cs;
    __syncthreads();

    float cn = 0.f;
    #pragma unroll
    for (int i = 0; i < 8; i++) cn += red[i];
    cn = fmaxf(sqrtf(cn), EPS);

    const float4* cen4 = (const float4*)cen;
    const float4 c0 = cen4[lane];
    const float4 c1 = cen4[lane + 32];

    for (int k = warp; k < KT; k += 8) {
        const int r = (k < K1) ? nbr[b * K1 + k] : nbr2[b * K2 + (k - K1)];
        const float4* src = (const float4*)(embeds + (size_t)r * H);
        const float4* wv  = (const float4*)((k < K1) ? wnb : wnb2);
        float4 e0 = src[lane];
        float4 e1 = src[lane + 32];
        const float4 w0 = wv[lane];
        const float4 w1 = wv[lane + 32];
        e0.x *= w0.x; e0.y *= w0.y; e0.z *= w0.z; e0.w *= w0.w;
        e1.x *= w1.x; e1.y *= w1.y; e1.z *= w1.z; e1.w *= w1.w;

        float d = e0.x * c0.x + e0.y * c0.y + e0.z * c0.z + e0.w * c0.w
                + e1.x * c1.x + e1.y * c1.y + e1.z * c1.z + e1.w * c1.w;
        float s = e0.x * e0.x + e0.y * e0.y + e0.z * e0.z + e0.w * e0.w
                + e1.x * e1.x + e1.y * e1.y + e1.z * e1.z + e1.w * e1.w;

        float4* dst = (float4*)(nb_s + k * H);
        dst[lane]      = e0;
        dst[lane + 32] = e1;

        d = wred_sum(d);
        s = wred_sum(s);
        if (lane == 0) { dots[k] = d; nrms[k] = s; }
    }
    __syncthreads();

    if (warp == 0) {
        const int ka = lane, kb = lane + 32;
        float cosA = -1e30f, cosB = -1e30f;
        if (ka < KT) cosA = dots[ka] / (cn * fmaxf(sqrtf(nrms[ka]), EPS));
        if (kb < KT) cosB = dots[kb] / (cn * fmaxf(sqrtf(nrms[kb]), EPS));
        float m = fmaxf(cosA, cosB);
        #pragma unroll
        for (int o = 16; o; o >>= 1) m = fmaxf(m, __shfl_xor_sync(0xFFFFFFFFu, m, o));
        float eA = (ka < KT) ? __expf(cosA - m) : 0.f;
        float eB = (kb < KT) ? __expf(cosB - m) : 0.f;
        const float ssum = wred_sum(eA + eB);
        const float inv = 1.f / ssum;
        if (ka < KT) wgt[ka] = eA * inv;
        if (kb < KT) wgt[kb] = eB * inv;
    }
    __syncthreads();

    float acc = 0.f;
    for (int k = 0; k < KT; k++)
        acc = fmaf(wgt[k], nb_s[k * H + tid], acc);
    const float rr = acc + c;

    g_rawret[(size_t)b * H + tid] = rr;

    float rs = wred_sum(rr * rr);
    if (lane == 0) red[warp] = rs;
    __syncthreads();
    if (tid == 0) {
        float t = 0.f;
        #pragma unroll
        for (int i = 0; i < 8; i++) t += red[i];
        g_rn[b] = fmaxf(sqrtf(t), EPS);
    }

    const int lbl = labels[b];
    atomicAdd(&g_csum[lbl * H + tid], rr);
    if (tid == 0) atomicAdd(&g_ccnt[lbl], 1.f);
}

// ---------------------------------------------------------------------------
// Kernel 2: class means + norms. 7 blocks x 256 threads.
// ---------------------------------------------------------------------------
__global__ void k2() {
    __shared__ float red[8];
    const int cc   = blockIdx.x;
    const int tid  = threadIdx.x;
    const int lane = tid & 31;
    const int warp = tid >> 5;
    const float v = g_csum[cc * H + tid] / fmaxf(g_ccnt[cc], 1.f);
    g_ave[cc * H + tid] = v;
    float s = wred_sum(v * v);
    if (lane == 0) red[warp] = s;
    __syncthreads();
    if (tid == 0) {
        float t = 0.f;
        #pragma unroll
        for (int i = 0; i < 8; i++) t += red[i];
        g_an[cc] = fmaxf(sqrtf(t), EPS);
    }
}

// ---------------------------------------------------------------------------
// Kernel 3: output. 1 warp per row, 8 rows per CTA. Interleaved butterflies.
// ---------------------------------------------------------------------------
__global__ void k3(float* __restrict__ out, int B) {
    __shared__ float ave_s[NB_CLASSES * H];
    __shared__ float an_s[NB_CLASSES];
    const int tid  = threadIdx.x;
    const int lane = tid & 31;
    const int warp = tid >> 5;
    for (int i = tid; i < NB_CLASSES * H; i += 256) ave_s[i] = g_ave[i];
    if (tid < NB_CLASSES) an_s[tid] = g_an[tid];
    __syncthreads();

    const int b = blockIdx.x * 8 + warp;
    if (b >= B) return;

    const float4* r4 = (const float4*)(g_rawret + (size_t)b * H);
    const float4 ra = __ldcs(&r4[lane]);
    const float4 rb = __ldcs(&r4[lane + 32]);

    float d[NB_CLASSES];
    #pragma unroll
    for (int cc = 0; cc < NB_CLASSES; cc++) {
        const float4* a4 = (const float4*)(ave_s + cc * H);
        const float4 a0 = a4[lane];
        const float4 a1 = a4[lane + 32];
        d[cc] = ra.x * a0.x + ra.y * a0.y + ra.z * a0.z + ra.w * a0.w
              + rb.x * a1.x + rb.y * a1.y + rb.z * a1.z + rb.w * a1.w;
    }
    #pragma unroll
    for (int o = 16; o; o >>= 1) {
        #pragma unroll
        for (int cc = 0; cc < NB_CLASSES; cc++)
            d[cc] += __shfl_xor_sync(0xFFFFFFFFu, d[cc], o);
    }

    const float rbn = g_rn[b];
    float m = -1e30f;
    #pragma unroll
    for (int cc = 0; cc < NB_CLASSES; cc++) {
        d[cc] = d[cc] / (rbn * an_s[cc]);
        m = fmaxf(m, d[cc]);
    }
    float s = 0.f;
    #pragma unroll
    for (int cc = 0; cc < NB_CLASSES; cc++) {
        d[cc] = __expf(d[cc] - m);
        s += d[cc];
    }
    const float inv = 1.f / s;
    if (lane < NB_CLASSES) {
        float v = 0.f;
        #pragma unroll
        for (int cc = 0; cc < NB_CLASSES; cc++)
            if (lane == cc) v = d[cc] * inv;
        __stcs(&out[b * NB_CLASSES + lane], v);
    }
}

// ---------------------------------------------------------------------------
extern "C" void kernel_launch(void* const* d_in, const int* in_sizes, int n_in,
                              void* d_out, int out_size) {
    const float* embeds = (const float*)d_in[0];
    const float* wself  = (const float*)d_in[1];
    const float* wnb    = (const float*)d_in[2];
    const float* wnb2   = (const float*)d_in[3];
    const int*   idx    = (const int*)d_in[4];
    const int*   labels = (const int*)d_in[5];
    const int*   nbr    = (const int*)d_in[6];
    const int*   nbr2   = (const int*)d_in[7];
    float* out = (float*)d_out;

    const int B  = in_sizes[4];
    const int K1 = in_sizes[6] / B;
    const int K2 = in_sizes[7] / B;
    const int KT = K1 + K2;
    const int N  = in_sizes[0] / H;

    if (K1 == 16 && K2 == 32 && N <= N_MAX) {
        // fp16 gather path
        const size_t smem = (size_t)KT * H * sizeof(__half)
                          + (size_t)(3 * H + 3 * KT + 8) * sizeof(float);
        static int attr_set = 0;
        if (!attr_set) {
            cudaFuncSetAttribute(k1s<16, 32>,
                                 cudaFuncAttributeMaxDynamicSharedMemorySize, (int)smem);
            attr_set = 1;
        }
        kc<<<1024, 256>>>(embeds, N * H / 8);
        k1s<16, 32><<<B, 256, smem>>>(embeds, wself, wnb, wnb2, idx, labels, nbr, nbr2);
    } else {
        const size_t smem = (size_t)(KT * H + H + 3 * KT + 32) * sizeof(float);
        cudaFuncSetAttribute(k1g, cudaFuncAttributeMaxDynamicSharedMemorySize, (int)smem);
        kc<<<1, 256>>>(embeds, 0);  // still zero accumulators
        k1g<<<B, 256, smem>>>(embeds, wself, wnb, wnb2, idx, labels, nbr, nbr2, K1, K2);
    }
    k2<<<NB_CLASSES, 256>>>();
    k3<<<(B + 7) / 8, 256>>>(out, B);
}

// round 4
// speedup vs baseline: 1.8875x; 1.5217x over previous
#include <cuda_runtime.h>
#include <cuda_fp16.h>
#include <math.h>

#define H 256
#define NB_CLASSES 7
#define B_MAX 14000
#define N_MAX 100000
#define EPS 1e-8f

// Scratch (allocation-free rule: __device__ globals)
__device__ __align__(16) __half g_eh[(size_t)N_MAX * H];  // fp16 embeds (51.2 MB)
__device__ float g_n1[N_MAX];                             // ||e * w_nb||^2
__device__ float g_n2[N_MAX];                             // ||e * w_nb2||^2
__device__ float g_rawret[B_MAX * H];
__device__ float g_rn[B_MAX];
__device__ float g_csum[NB_CLASSES * H];
__device__ float g_ccnt[NB_CLASSES];
__device__ float g_ave[NB_CLASSES * H];
__device__ float g_an[NB_CLASSES];

__device__ __forceinline__ float wred_sum(float v) {
    #pragma unroll
    for (int o = 16; o; o >>= 1) v += __shfl_xor_sync(0xFFFFFFFFu, v, o);
    return v;
}

// ---------------------------------------------------------------------------
// Kernel C: fp32 -> fp16 table + per-row weighted norms. Warp per row.
// Block 0 also zeroes the class accumulators.
// ---------------------------------------------------------------------------
__global__ void kc(const float* __restrict__ embeds,
                   const float* __restrict__ wnb,
                   const float* __restrict__ wnb2,
                   int N) {
    if (blockIdx.x == 0) {
        for (int j = threadIdx.x; j < NB_CLASSES * H; j += blockDim.x) g_csum[j] = 0.f;
        if (threadIdx.x < NB_CLASSES) g_ccnt[threadIdx.x] = 0.f;
    }
    const int lane = threadIdx.x & 31;
    const int gw = (blockIdx.x * blockDim.x + threadIdx.x) >> 5;
    const int nw = (gridDim.x * blockDim.x) >> 5;

    // per-lane weight slices (channels [8*lane, 8*lane+8))
    const float4 wa0 = ((const float4*)wnb)[2 * lane];
    const float4 wa1 = ((const float4*)wnb)[2 * lane + 1];
    const float4 wb0 = ((const float4*)wnb2)[2 * lane];
    const float4 wb1 = ((const float4*)wnb2)[2 * lane + 1];
    float wav[8] = {wa0.x, wa0.y, wa0.z, wa0.w, wa1.x, wa1.y, wa1.z, wa1.w};
    float wbv[8] = {wb0.x, wb0.y, wb0.z, wb0.w, wb1.x, wb1.y, wb1.z, wb1.w};

    for (int r = gw; r < N; r += nw) {
        const float4* src = (const float4*)(embeds + (size_t)r * H);
        const float4 a = src[2 * lane];
        const float4 b = src[2 * lane + 1];
        float e[8] = {a.x, a.y, a.z, a.w, b.x, b.y, b.z, b.w};

        float n1 = 0.f, n2 = 0.f;
        #pragma unroll
        for (int i = 0; i < 8; i++) {
            const float x1 = e[i] * wav[i];
            const float x2 = e[i] * wbv[i];
            n1 = fmaf(x1, x1, n1);
            n2 = fmaf(x2, x2, n2);
        }

        union { uint4 u; __half2 h[4]; } pk;
        #pragma unroll
        for (int i = 0; i < 4; i++)
            pk.h[i] = __float22half2_rn(make_float2(e[2 * i], e[2 * i + 1]));
        ((uint4*)(g_eh + (size_t)r * H))[lane] = pk.u;

        #pragma unroll
        for (int o = 16; o; o >>= 1) {
            n1 += __shfl_xor_sync(0xFFFFFFFFu, n1, o);
            n2 += __shfl_xor_sync(0xFFFFFFFFu, n2, o);
        }
        if (lane == 0) { g_n1[r] = n1; g_n2[r] = n2; }
    }
}

// ---------------------------------------------------------------------------
// Kernel 1 (K1=16, K2=32): 1 CTA per row b, 128 threads (4 warps), occ 8.
//  - cp.async raw fp16 rows into SMEM (no register payload)
//  - prompt weights folded into center -> dots against c1/c2 lane slices
//  - neighbor norms precomputed by kc
//  - weighted sum keeps 1-hop / 2-hop partials, scales once at the end
// ---------------------------------------------------------------------------
template<int K1, int K2>
__global__ void __launch_bounds__(128, 8)
k1s(const float* __restrict__ embeds,
    const float* __restrict__ wself,
    const float* __restrict__ wnb,
    const float* __restrict__ wnb2,
    const int* __restrict__ idx,
    const int* __restrict__ labels,
    const int* __restrict__ nbr,
    const int* __restrict__ nbr2) {
    constexpr int KT = K1 + K2;   // 48
    constexpr int JP = KT / 4;    // 12 rows per warp

    __shared__ __align__(16) __half nb_h[KT * H];  // raw fp16 rows (24.6 KB)
    __shared__ float cen[H];
    __shared__ int   rix[KT];
    __shared__ float nrm_s[KT];
    __shared__ float dots[KT];
    __shared__ float wgt[KT];
    __shared__ float red[4];

    const int b    = blockIdx.x;
    const int tid  = threadIdx.x;
    const int lane = tid & 31;
    const int warp = tid >> 5;

    // center: thread owns channels 2t, 2t+1
    const int crow = idx[b];
    const float2 ev = ((const float2*)(embeds + (size_t)crow * H))[tid];
    const float2 ws = ((const float2*)wself)[tid];
    const float2 cv = make_float2(ev.x * ws.x, ev.y * ws.y);
    ((float2*)cen)[tid] = cv;
    float cs = cv.x * cv.x + cv.y * cv.y;
    cs = wred_sum(cs);
    if (lane == 0) red[warp] = cs;

    // neighbor indices + precomputed norms
    if (tid < KT) {
        const int r = (tid < K1) ? nbr[b * K1 + tid] : nbr2[b * K2 + tid - K1];
        rix[tid] = r;
        nrm_s[tid] = (tid < K1) ? g_n1[r] : g_n2[r];
    }
    __syncthreads();

    const float cn = fmaxf(sqrtf(red[0] + red[1] + red[2] + red[3]), EPS);

    // cp.async gathers: warp w copies rows k = w + 4*j (16B per lane per row)
    #pragma unroll
    for (int j = 0; j < JP; j++) {
        const int k = warp + 4 * j;
        const __half* gp = g_eh + (size_t)rix[k] * H + lane * 8;
        const unsigned sp =
            (unsigned)__cvta_generic_to_shared(nb_h + k * H + lane * 8);
        asm volatile("cp.async.cg.shared.global [%0], [%1], 16;\n"
                     :: "r"(sp), "l"(gp) : "memory");
    }
    asm volatile("cp.async.commit_group;\n" ::: "memory");

    // while TMA... while cp.async in flight: per-lane c1/c2 slices
    float c1v[8], c2v[8];
    {
        const float4 ca = ((const float4*)cen)[2 * lane];
        const float4 cb = ((const float4*)cen)[2 * lane + 1];
        const float ce[8] = {ca.x, ca.y, ca.z, ca.w, cb.x, cb.y, cb.z, cb.w};
        const float4 wa0 = ((const float4*)wnb)[2 * lane];
        const float4 wa1 = ((const float4*)wnb)[2 * lane + 1];
        const float4 wb0 = ((const float4*)wnb2)[2 * lane];
        const float4 wb1 = ((const float4*)wnb2)[2 * lane + 1];
        const float wav[8] = {wa0.x, wa0.y, wa0.z, wa0.w, wa1.x, wa1.y, wa1.z, wa1.w};
        const float wbv[8] = {wb0.x, wb0.y, wb0.z, wb0.w, wb1.x, wb1.y, wb1.z, wb1.w};
        #pragma unroll
        for (int i = 0; i < 8; i++) {
            c1v[i] = ce[i] * wav[i];
            c2v[i] = ce[i] * wbv[i];
        }
    }

    asm volatile("cp.async.wait_group 0;\n" ::: "memory");
    __syncthreads();

    // dots: warp w rows k = w + 4j; j < K1/4 -> 1-hop (c1), else c2
    float d[JP];
    #pragma unroll
    for (int j = 0; j < JP; j++) {
        const int k = warp + 4 * j;
        union { uint4 u; __half2 h[4]; } pk;
        pk.u = ((const uint4*)(nb_h + k * H))[lane];
        const float* cw = (j < (K1 / 4)) ? c1v : c2v;
        const float2 v0 = __half22float2(pk.h[0]);
        const float2 v1 = __half22float2(pk.h[1]);
        const float2 v2 = __half22float2(pk.h[2]);
        const float2 v3 = __half22float2(pk.h[3]);
        d[j] = v0.x * cw[0] + v0.y * cw[1] + v1.x * cw[2] + v1.y * cw[3]
             + v2.x * cw[4] + v2.y * cw[5] + v3.x * cw[6] + v3.y * cw[7];
    }
    #pragma unroll
    for (int o = 16; o; o >>= 1) {
        #pragma unroll
        for (int j = 0; j < JP; j++)
            d[j] += __shfl_xor_sync(0xFFFFFFFFu, d[j], o);
    }
    if (lane == 0) {
        #pragma unroll
        for (int j = 0; j < JP; j++) dots[warp + 4 * j] = d[j];
    }
    __syncthreads();

    // softmax over KT cosine sims (warp 0)
    if (warp == 0) {
        const int ka = lane, kb = lane + 32;
        float cosA = -1e30f, cosB = -1e30f;
        if (ka < KT) cosA = dots[ka] / (cn * fmaxf(sqrtf(nrm_s[ka]), EPS));
        if (kb < KT) cosB = dots[kb] / (cn * fmaxf(sqrtf(nrm_s[kb]), EPS));
        float m = fmaxf(cosA, cosB);
        #pragma unroll
        for (int o = 16; o; o >>= 1) m = fmaxf(m, __shfl_xor_sync(0xFFFFFFFFu, m, o));
        const float eA = (ka < KT) ? __expf(cosA - m) : 0.f;
        const float eB = (kb < KT) ? __expf(cosB - m) : 0.f;
        const float inv = 1.f / wred_sum(eA + eB);
        if (ka < KT) wgt[ka] = eA * inv;
        if (kb < KT) wgt[kb] = eB * inv;
    }
    __syncthreads();

    // weighted sum: thread owns channels 2t, 2t+1; 1-hop/2-hop partials
    float ax = 0.f, ay = 0.f, bx = 0.f, by = 0.f;
    #pragma unroll
    for (int k = 0; k < K1; k++) {
        const float2 v = __half22float2(((const __half2*)(nb_h + k * H))[tid]);
        const float w = wgt[k];
        ax = fmaf(w, v.x, ax); ay = fmaf(w, v.y, ay);
    }
    #pragma unroll
    for (int k = K1; k < KT; k++) {
        const float2 v = __half22float2(((const __half2*)(nb_h + k * H))[tid]);
        const float w = wgt[k];
        bx = fmaf(w, v.x, bx); by = fmaf(w, v.y, by);
    }
    const float2 wa = ((const float2*)wnb)[tid];
    const float2 wb = ((const float2*)wnb2)[tid];
    const float rx = ax * wa.x + bx * wb.x + cv.x;
    const float ry = ay * wa.y + by * wb.y + cv.y;
    __stcs((float2*)(g_rawret + (size_t)b * H) + tid, make_float2(rx, ry));

    float rs = rx * rx + ry * ry;
    rs = wred_sum(rs);
    __syncthreads();  // red reuse barrier
    if (lane == 0) red[warp] = rs;
    __syncthreads();
    if (tid == 0)
        g_rn[b] = fmaxf(sqrtf(red[0] + red[1] + red[2] + red[3]), EPS);

    const int lbl = labels[b];
    atomicAdd(&g_csum[lbl * H + 2 * tid],     rx);
    atomicAdd(&g_csum[lbl * H + 2 * tid + 1], ry);
    if (tid == 0) atomicAdd(&g_ccnt[lbl], 1.f);
}

// ---------------------------------------------------------------------------
// Generic fallback (any K1/K2), fp32 path
// ---------------------------------------------------------------------------
__global__ void kz() {
    int i = blockIdx.x * blockDim.x + threadIdx.x;
    if (i < NB_CLASSES * H) g_csum[i] = 0.f;
    if (i < NB_CLASSES) g_ccnt[i] = 0.f;
}

__global__ void k1g(const float* __restrict__ embeds,
                    const float* __restrict__ wself,
                    const float* __restrict__ wnb,
                    const float* __restrict__ wnb2,
                    const int* __restrict__ idx,
                    const int* __restrict__ labels,
                    const int* __restrict__ nbr,
                    const int* __restrict__ nbr2,
                    int K1, int K2) {
    extern __shared__ float sh[];
    const int KT = K1 + K2;
    float* nb_s = sh;
    float* cen  = sh + KT * H;
    float* dots = cen + H;
    float* nrms = dots + KT;
    float* wgt  = nrms + KT;
    float* red  = wgt + KT;

    const int b    = blockIdx.x;
    const int tid  = threadIdx.x;
    const int lane = tid & 31;
    const int warp = tid >> 5;

    const int crow = idx[b];
    const float c = embeds[(size_t)crow * H + tid] * wself[tid];
    cen[tid] = c;
    float cs = wred_sum(c * c);
    if (lane == 0) red[warp] = cs;
    __syncthreads();

    float cn = 0.f;
    #pragma unroll
    for (int i = 0; i < 8; i++) cn += red[i];
    cn = fmaxf(sqrtf(cn), EPS);

    const float4* cen4 = (const float4*)cen;
    const float4 c0 = cen4[lane];
    const float4 c1 = cen4[lane + 32];

    for (int k = warp; k < KT; k += 8) {
        const int r = (k < K1) ? nbr[b * K1 + k] : nbr2[b * K2 + (k - K1)];
        const float4* src = (const float4*)(embeds + (size_t)r * H);
        const float4* wv  = (const float4*)((k < K1) ? wnb : wnb2);
        float4 e0 = src[lane];
        float4 e1 = src[lane + 32];
        const float4 w0 = wv[lane];
        const float4 w1 = wv[lane + 32];
        e0.x *= w0.x; e0.y *= w0.y; e0.z *= w0.z; e0.w *= w0.w;
        e1.x *= w1.x; e1.y *= w1.y; e1.z *= w1.z; e1.w *= w1.w;

        float d = e0.x * c0.x + e0.y * c0.y + e0.z * c0.z + e0.w * c0.w
                + e1.x * c1.x + e1.y * c1.y + e1.z * c1.z + e1.w * c1.w;
        float s = e0.x * e0.x + e0.y * e0.y + e0.z * e0.z + e0.w * e0.w
                + e1.x * e1.x + e1.y * e1.y + e1.z * e1.z + e1.w * e1.w;

        float4* dst = (float4*)(nb_s + k * H);
        dst[lane]      = e0;
        dst[lane + 32] = e1;

        d = wred_sum(d);
        s = wred_sum(s);
        if (lane == 0) { dots[k] = d; nrms[k] = s; }
    }
    __syncthreads();

    if (warp == 0) {
        const int ka = lane, kb = lane + 32;
        float cosA = -1e30f, cosB = -1e30f;
        if (ka < KT) cosA = dots[ka] / (cn * fmaxf(sqrtf(nrms[ka]), EPS));
        if (kb < KT) cosB = dots[kb] / (cn * fmaxf(sqrtf(nrms[kb]), EPS));
        float m = fmaxf(cosA, cosB);
        #pragma unroll
        for (int o = 16; o; o >>= 1) m = fmaxf(m, __shfl_xor_sync(0xFFFFFFFFu, m, o));
        float eA = (ka < KT) ? __expf(cosA - m) : 0.f;
        float eB = (kb < KT) ? __expf(cosB - m) : 0.f;
        const float inv = 1.f / wred_sum(eA + eB);
        if (ka < KT) wgt[ka] = eA * inv;
        if (kb < KT) wgt[kb] = eB * inv;
    }
    __syncthreads();

    float acc = 0.f;
    for (int k = 0; k < KT; k++)
        acc = fmaf(wgt[k], nb_s[k * H + tid], acc);
    const float rr = acc + c;

    g_rawret[(size_t)b * H + tid] = rr;

    float rs = wred_sum(rr * rr);
    __syncthreads();
    if (lane == 0) red[warp] = rs;
    __syncthreads();
    if (tid == 0) {
        float t = 0.f;
        #pragma unroll
        for (int i = 0; i < 8; i++) t += red[i];
        g_rn[b] = fmaxf(sqrtf(t), EPS);
    }

    const int lbl = labels[b];
    atomicAdd(&g_csum[lbl * H + tid], rr);
    if (tid == 0) atomicAdd(&g_ccnt[lbl], 1.f);
}

// ---------------------------------------------------------------------------
// Kernel 2: class means + norms. 7 blocks x 256 threads.
// ---------------------------------------------------------------------------
__global__ void k2() {
    __shared__ float red[8];
    const int cc   = blockIdx.x;
    const int tid  = threadIdx.x;
    const int lane = tid & 31;
    const int warp = tid >> 5;
    const float v = g_csum[cc * H + tid] / fmaxf(g_ccnt[cc], 1.f);
    g_ave[cc * H + tid] = v;
    float s = wred_sum(v * v);
    if (lane == 0) red[warp] = s;
    __syncthreads();
    if (tid == 0) {
        float t = 0.f;
        #pragma unroll
        for (int i = 0; i < 8; i++) t += red[i];
        g_an[cc] = fmaxf(sqrtf(t), EPS);
    }
}

// ---------------------------------------------------------------------------
// Kernel 3: output. 1 warp per row, 8 rows per CTA. Interleaved butterflies.
// ---------------------------------------------------------------------------
__global__ void k3(float* __restrict__ out, int B) {
    __shared__ float ave_s[NB_CLASSES * H];
    __shared__ float an_s[NB_CLASSES];
    const int tid  = threadIdx.x;
    const int lane = tid & 31;
    const int warp = tid >> 5;
    for (int i = tid; i < NB_CLASSES * H; i += 256) ave_s[i] = g_ave[i];
    if (tid < NB_CLASSES) an_s[tid] = g_an[tid];
    __syncthreads();

    const int b = blockIdx.x * 8 + warp;
    if (b >= B) return;

    const float4* r4 = (const float4*)(g_rawret + (size_t)b * H);
    const float4 ra = __ldcs(&r4[lane]);
    const float4 rb = __ldcs(&r4[lane + 32]);

    float d[NB_CLASSES];
    #pragma unroll
    for (int cc = 0; cc < NB_CLASSES; cc++) {
        const float4* a4 = (const float4*)(ave_s + cc * H);
        const float4 a0 = a4[lane];
        const float4 a1 = a4[lane + 32];
        d[cc] = ra.x * a0.x + ra.y * a0.y + ra.z * a0.z + ra.w * a0.w
              + rb.x * a1.x + rb.y * a1.y + rb.z * a1.z + rb.w * a1.w;
    }
    #pragma unroll
    for (int o = 16; o; o >>= 1) {
        #pragma unroll
        for (int cc = 0; cc < NB_CLASSES; cc++)
            d[cc] += __shfl_xor_sync(0xFFFFFFFFu, d[cc], o);
    }

    const float rbn = g_rn[b];
    float m = -1e30f;
    #pragma unroll
    for (int cc = 0; cc < NB_CLASSES; cc++) {
        d[cc] = d[cc] / (rbn * an_s[cc]);
        m = fmaxf(m, d[cc]);
    }
    float s = 0.f;
    #pragma unroll
    for (int cc = 0; cc < NB_CLASSES; cc++) {
        d[cc] = __expf(d[cc] - m);
        s += d[cc];
    }
    const float inv = 1.f / s;
    if (lane < NB_CLASSES) {
        float v = 0.f;
        #pragma unroll
        for (int cc = 0; cc < NB_CLASSES; cc++)
            if (lane == cc) v = d[cc] * inv;
        __stcs(&out[b * NB_CLASSES + lane], v);
    }
}

// ---------------------------------------------------------------------------
extern "C" void kernel_launch(void* const* d_in, const int* in_sizes, int n_in,
                              void* d_out, int out_size) {
    const float* embeds = (const float*)d_in[0];
    const float* wself  = (const float*)d_in[1];
    const float* wnb    = (const float*)d_in[2];
    const float* wnb2   = (const float*)d_in[3];
    const int*   idx    = (const int*)d_in[4];
    const int*   labels = (const int*)d_in[5];
    const int*   nbr    = (const int*)d_in[6];
    const int*   nbr2   = (const int*)d_in[7];
    float* out = (float*)d_out;

    const int B  = in_sizes[4];
    const int K1 = in_sizes[6] / B;
    const int K2 = in_sizes[7] / B;
    const int KT = K1 + K2;
    const int N  = in_sizes[0] / H;

    if (K1 == 16 && K2 == 32 && N <= N_MAX && B <= B_MAX) {
        kc<<<2048, 256>>>(embeds, wnb, wnb2, N);
        k1s<16, 32><<<B, 128>>>(embeds, wself, wnb, wnb2, idx, labels, nbr, nbr2);
    } else {
        const size_t smem = (size_t)(KT * H + H + 3 * KT + 32) * sizeof(float);
        cudaFuncSetAttribute(k1g, cudaFuncAttributeMaxDynamicSharedMemorySize, (int)smem);
        kz<<<NB_CLASSES, 256>>>();
        k1g<<<B, 256, smem>>>(embeds, wself, wnb, wnb2, idx, labels, nbr, nbr2, K1, K2);
    }
    k2<<<NB_CLASSES, 256>>>();
    k3<<<(B + 7) / 8, 256>>>(out, B);
}